// round 7
// baseline (speedup 1.0000x reference)
#include <cuda_runtime.h>
#include <cstdint>

#define SEQ   4096
#define BATCH 4
#define DIM   1024
#define RANK  64
#define NROW  (BATCH * SEQ)   // 16384
#define NTILE 32
#define TRI   528             // upper-tri tiles per batch

// Scratch (__device__ globals per allocation rules)
__device__ float g_pA[NROW * RANK];   // p, A-fragment layout (32KB / 128-row blk)
__device__ float g_pB[NROW * RANK];   // p, B-fragment layout
__device__ float g_sq[NROW];          // row squared norms (of tf32-rounded p)

// ---------------- helpers ----------------
__device__ __forceinline__ uint32_t smem_u32(const void* p) {
    uint32_t a;
    asm("{ .reg .u64 t; cvta.to.shared.u64 t, %1; cvt.u32.u64 %0, t; }"
        : "=r"(a) : "l"(p));
    return a;
}
__device__ __forceinline__ void cpasync16(uint32_t s, const void* g) {
    asm volatile("cp.async.cg.shared.global [%0], [%1], 16;"
                 :: "r"(s), "l"(g) : "memory");
}
__device__ __forceinline__ uint32_t tf32u(float f) {
    uint32_t t;
    asm("cvt.rna.tf32.f32 %0, %1;" : "=r"(t) : "f"(f));
    return t;
}
__device__ __forceinline__ float tf32r(float f) { return __uint_as_float(tf32u(f)); }
__device__ __forceinline__ void mma_tf32(float* d, const uint32_t* a,
                                         uint32_t b0, uint32_t b1) {
    asm volatile(
        "mma.sync.aligned.m16n8k8.row.col.f32.tf32.tf32.f32 "
        "{%0,%1,%2,%3}, {%4,%5,%6,%7}, {%8,%9}, {%0,%1,%2,%3};"
        : "+f"(d[0]), "+f"(d[1]), "+f"(d[2]), "+f"(d[3])
        : "r"(a[0]), "r"(a[1]), "r"(a[2]), "r"(a[3]), "r"(b0), "r"(b1));
}

// ============================================================
// Kernel 1: proj GEMM with inline fragment prep.
// 256 CTAs x 64 rows, K=1024 in 16 chunks. 3-stage cp.async pipeline
// for x; proj chunk loaded raw (L2-hot), converted+scattered via regs.
// ============================================================
#define XST 68
#define XBUF (64 * XST)          // 4352 floats
#define PBUF 4096                // floats (proj fragments for one chunk)
#define STAGE (XBUF + PBUF)      // 8448 floats = 33792 B
#define PROJ_SMEM (3 * STAGE * 4)  // 101376 B -> 2 CTA/SM

__global__ void __launch_bounds__(256, 2) proj_mma_kernel(
    const float* __restrict__ x, const float* __restrict__ proj) {
    extern __shared__ __align__(16) float smf[];
    __shared__ float s_part[2][64];

    const int tid = threadIdx.x, wid = tid >> 5, lane = tid & 31;
    const int gid = lane >> 2, tig = lane & 3;
    const int wm = wid & 3, wn = wid >> 2;
    const int rowbase = blockIdx.x * 64;
    const uint32_t sbase = smem_u32(smf);

    float acc[4][4];
#pragma unroll
    for (int i = 0; i < 4; i++)
#pragma unroll
        for (int j = 0; j < 4; j++) acc[i][j] = 0.f;

    auto load_x = [&](int it, int buf) {
        const uint32_t sb = sbase + (uint32_t)(buf * STAGE) * 4;
        const float* src = x + (size_t)rowbase * DIM + it * 64;
#pragma unroll
        for (int l = 0; l < 4; l++) {
            int idx = tid + l * 256;
            int r = idx >> 4, c4 = (idx & 15) << 2;
            cpasync16(sb + (uint32_t)(r * XST + c4) * 4,
                      src + (size_t)r * DIM + c4);
        }
        asm volatile("cp.async.commit_group;" ::: "memory");
    };
    auto ldg_proj = [&](int it, float4* pv) {
#pragma unroll
        for (int l = 0; l < 4; l++) {
            int idx = tid + l * 256;
            int kk = idx >> 4, n4 = (idx & 15) << 2;
            pv[l] = *(const float4*)(proj + (size_t)(it * 64 + kk) * RANK + n4);
        }
    };
    auto sts_proj = [&](int buf, const float4* pv) {
        float* pd = smf + buf * STAGE + XBUF;
#pragma unroll
        for (int l = 0; l < 4; l++) {
            int idx = tid + l * 256;
            int kk = idx >> 4, n4 = (idx & 15) << 2;
            int kt = kk >> 3, f = (kk >> 2) & 1, k3 = kk & 3;
            const float* vp = (const float*)&pv[l];
#pragma unroll
            for (int j = 0; j < 4; j++) {
                int n = n4 + j;
                pd[((n >> 3) * 8 + kt) * 64 + ((n & 7) * 4 + k3) * 2 + f] =
                    tf32r(vp[j]);
            }
        }
    };

    load_x(0, 0);
    load_x(1, 1);
    load_x(2, 2);
    float4 pv[4];
    ldg_proj(0, pv);

    int buf = 0;
    for (int it = 0; it < 16; ++it) {
        if (it <= 13)      asm volatile("cp.async.wait_group 2;" ::: "memory");
        else if (it == 14) asm volatile("cp.async.wait_group 1;" ::: "memory");
        else               asm volatile("cp.async.wait_group 0;" ::: "memory");

        sts_proj(buf, pv);
        if (it + 1 < 16) ldg_proj(it + 1, pv);
        __syncthreads();   // x arrival + proj STS visible to all warps

        const float* xb = smf + buf * STAGE;
        const float* pb = xb + XBUF;
        const int r0 = wm * 16 + gid;
#pragma unroll
        for (int kt = 0; kt < 8; kt++) {
            const int c = kt * 8 + tig;
            uint32_t a[4];
            a[0] = tf32u(xb[r0 * XST + c]);
            a[1] = tf32u(xb[(r0 + 8) * XST + c]);
            a[2] = tf32u(xb[r0 * XST + c + 4]);
            a[3] = tf32u(xb[(r0 + 8) * XST + c + 4]);
#pragma unroll
            for (int nt = 0; nt < 4; nt++) {
                const int ng = wn * 4 + nt;
                const uint2 bb = *(const uint2*)(pb + (ng * 8 + kt) * 64 + lane * 2);
                mma_tf32(acc[nt], a, bb.x, bb.y);
            }
        }
        __syncthreads();   // all warps done with buf before refill
        if (it + 3 < 16) load_x(it + 3, buf);
        buf = (buf == 2) ? 0 : buf + 1;
    }

    // ---- epilogue: round to tf32, sq norms, scatter to fragment layouts ----
    float vals[4][4];
    float sq1 = 0.f, sq2 = 0.f;
#pragma unroll
    for (int nt = 0; nt < 4; nt++) {
#pragma unroll
        for (int j = 0; j < 4; j++) vals[nt][j] = tf32r(acc[nt][j]);
        sq1 += vals[nt][0] * vals[nt][0] + vals[nt][1] * vals[nt][1];
        sq2 += vals[nt][2] * vals[nt][2] + vals[nt][3] * vals[nt][3];
    }
    sq1 += __shfl_xor_sync(0xffffffffu, sq1, 1);
    sq1 += __shfl_xor_sync(0xffffffffu, sq1, 2);
    sq2 += __shfl_xor_sync(0xffffffffu, sq2, 1);
    sq2 += __shfl_xor_sync(0xffffffffu, sq2, 2);

    const int r1 = wm * 16 + gid, r2 = r1 + 8;
    if (tig == 0) {
        s_part[wn][r1] = sq1;
        s_part[wn][r2] = sq2;
    }
    __syncthreads();
    if (tid < 64) g_sq[rowbase + tid] = s_part[0][tid] + s_part[1][tid];

    const int bb = blockIdx.x >> 1;
    const int half = (blockIdx.x & 1) * 64;
    float* gA = g_pA + (size_t)bb * 8192;
    float* gB = g_pB + (size_t)bb * 8192;
#pragma unroll
    for (int nt = 0; nt < 4; nt++) {
#pragma unroll
        for (int jj = 0; jj < 4; jj++) {
            const int lr = half + ((jj >= 2) ? r2 : r1);
            const int c = wn * 32 + nt * 8 + 2 * tig + (jj & 1);
            const float v = vals[nt][jj];
            {   // A-fragment layout
                int mt = lr >> 4, kt = c >> 3, rr = lr & 15, cc = c & 7;
                gA[(mt * 8 + kt) * 128 + ((rr & 7) * 4 + (cc & 3)) * 4 +
                   (rr >> 3) + 2 * (cc >> 2)] = v;
            }
            {   // B-fragment layout
                int ntb = lr >> 3, kt = c >> 3, nn = lr & 7, kkb = c & 7;
                gB[(ntb * 8 + kt) * 64 + (nn * 4 + (kkb & 3)) * 2 + (kkb >> 2)] = v;
            }
        }
    }
}

// ============================================================
// Kernel 2: dist, symmetric, 512 threads (16 warps, 32x32 warp tile).
// One CTA per upper-tri 128x128 tile; 2 CTA/SM -> 50% occupancy.
// ============================================================
#define TS_STRIDE 140
#define DIST_SMEM (128 * TS_STRIDE * 4)   // 71680 B

__global__ void __launch_bounds__(512, 2) dist_mma_kernel(
    float* __restrict__ out) {
    extern __shared__ __align__(16) float smf[];
    __shared__ float s_sqA[128], s_sqB[128];

    const int tid = threadIdx.x, wid = tid >> 5, lane = tid & 31;
    const int gid = lane >> 2, tig = lane & 3;
    const int bz = blockIdx.z;

    // decode upper-triangular (i <= j) tile index
    const int t = blockIdx.x;
    int i = (int)(32.5f - sqrtf(32.5f * 32.5f - 2.0f * (float)t));
    if (i > 31) i = 31;
    while (i > 0 && (i * 32 - i * (i - 1) / 2) > t) i--;
    while (((i + 1) * 32 - (i + 1) * i / 2) <= t) i++;
    const int j = i + (t - (i * 32 - i * (i - 1) / 2));

    const int ablk = bz * NTILE + i, bblk = bz * NTILE + j;
    const uint32_t sbase = smem_u32(smf);

    const float4* gA = (const float4*)(g_pA + (size_t)ablk * 8192);
    const float4* gB = (const float4*)(g_pB + (size_t)bblk * 8192);
#pragma unroll
    for (int l = 0; l < 4; l++) {
        int idx = tid + l * 512;
        cpasync16(sbase + (uint32_t)idx * 16, gA + idx);
        cpasync16(sbase + 32768u + (uint32_t)idx * 16, gB + idx);
    }
    asm volatile("cp.async.commit_group;" ::: "memory");
    if (tid < 128) s_sqA[tid] = g_sq[ablk * 128 + tid];
    else if (tid < 256) s_sqB[tid - 128] = g_sq[bblk * 128 + (tid - 128)];
    asm volatile("cp.async.wait_group 0;" ::: "memory");
    __syncthreads();

    const int wm = wid & 3, wn = wid >> 2;   // 4 m-groups x 4 n-groups
    const float* As = smf;
    const float* Bs = smf + 8192;

    float acc[2][4][4];
#pragma unroll
    for (int a = 0; a < 2; a++)
#pragma unroll
        for (int b = 0; b < 4; b++)
#pragma unroll
            for (int c = 0; c < 4; c++) acc[a][b][c] = 0.f;

#pragma unroll
    for (int kt = 0; kt < 8; kt++) {
        uint4 a[2];
        uint2 b[4];
#pragma unroll
        for (int mt = 0; mt < 2; mt++)
            a[mt] = *(const uint4*)(As + ((wm * 2 + mt) * 8 + kt) * 128 + lane * 4);
#pragma unroll
        for (int nt = 0; nt < 4; nt++)
            b[nt] = *(const uint2*)(Bs + ((wn * 4 + nt) * 8 + kt) * 64 + lane * 2);
#pragma unroll
        for (int mt = 0; mt < 2; mt++)
#pragma unroll
            for (int nt = 0; nt < 4; nt++)
                mma_tf32(acc[mt][nt], (const uint32_t*)&a[mt], b[nt].x, b[nt].y);
    }

    // ---- finalize values (clamped distances) in regs ----
#pragma unroll
    for (int mt = 0; mt < 2; mt++) {
        const int rl1 = wm * 32 + mt * 16 + gid, rl2 = rl1 + 8;
        const float sA1 = s_sqA[rl1], sA2 = s_sqA[rl2];
#pragma unroll
        for (int nt = 0; nt < 4; nt++) {
            const int cl = wn * 32 + nt * 8 + 2 * tig;
            const float sB0 = s_sqB[cl], sB1 = s_sqB[cl + 1];
            acc[mt][nt][0] = fmaxf(sA1 + sB0 - 2.f * acc[mt][nt][0], 0.f);
            acc[mt][nt][1] = fmaxf(sA1 + sB1 - 2.f * acc[mt][nt][1], 0.f);
            acc[mt][nt][2] = fmaxf(sA2 + sB0 - 2.f * acc[mt][nt][2], 0.f);
            acc[mt][nt][3] = fmaxf(sA2 + sB1 - 2.f * acc[mt][nt][3], 0.f);
        }
    }

    // ---- direct tile write (rows i-block, cols j-block), evict-first ----
#pragma unroll
    for (int mt = 0; mt < 2; mt++) {
        const int rl1 = wm * 32 + mt * 16 + gid;
        float* o1 = out + ((size_t)bz * SEQ + i * 128 + rl1) * SEQ + j * 128;
        float* o2 = o1 + (size_t)8 * SEQ;
#pragma unroll
        for (int nt = 0; nt < 4; nt++) {
            const int cl = wn * 32 + nt * 8 + 2 * tig;
            __stcs((float2*)(o1 + cl), make_float2(acc[mt][nt][0], acc[mt][nt][1]));
            __stcs((float2*)(o2 + cl), make_float2(acc[mt][nt][2], acc[mt][nt][3]));
        }
    }

    // ---- transposed tile write (off-diagonal only) ----
    if (i != j) {
        __syncthreads();   // done reading As/Bs; reuse smem as transpose buffer
        float* Ts = smf;
#pragma unroll
        for (int mt = 0; mt < 2; mt++) {
            const int rl1 = wm * 32 + mt * 16 + gid, rl2 = rl1 + 8;
#pragma unroll
            for (int nt = 0; nt < 4; nt++) {
                const int cl = wn * 32 + nt * 8 + 2 * tig;
                Ts[(cl + 0) * TS_STRIDE + rl1] = acc[mt][nt][0];
                Ts[(cl + 1) * TS_STRIDE + rl1] = acc[mt][nt][1];
                Ts[(cl + 0) * TS_STRIDE + rl2] = acc[mt][nt][2];
                Ts[(cl + 1) * TS_STRIDE + rl2] = acc[mt][nt][3];
            }
        }
        __syncthreads();
#pragma unroll
        for (int l = 0; l < 8; l++) {
            int idx = tid + l * 512;
            int c = idx >> 5, r4 = (idx & 31) << 2;
            float4 v = *(const float4*)(Ts + c * TS_STRIDE + r4);
            __stcs((float4*)(out + ((size_t)bz * SEQ + j * 128 + c) * SEQ +
                             i * 128 + r4), v);
        }
    }
}

// ============================================================
extern "C" void kernel_launch(void* const* d_in, const int* in_sizes, int n_in,
                              void* d_out, int out_size) {
    const float* x = (const float*)d_in[0];
    const float* proj = (const float*)d_in[1];
    float* out = (float*)d_out;

    cudaFuncSetAttribute(proj_mma_kernel,
                         cudaFuncAttributeMaxDynamicSharedMemorySize, PROJ_SMEM);
    proj_mma_kernel<<<NROW / 64, 256, PROJ_SMEM>>>(x, proj);

    cudaFuncSetAttribute(dist_mma_kernel,
                         cudaFuncAttributeMaxDynamicSharedMemorySize, DIST_SMEM);
    dim3 grid(TRI, 1, BATCH);
    dist_mma_kernel<<<grid, 512, DIST_SMEM>>>(out);
}

// round 8
// speedup vs baseline: 1.3592x; 1.3592x over previous
#include <cuda_runtime.h>
#include <cstdint>

#define SEQ   4096
#define BATCH 4
#define DIM   1024
#define RANK  64
#define NROW  (BATCH * SEQ)   // 16384
#define NTILE 32
#define TRI   528             // upper-tri tiles per batch

// Scratch (__device__ globals per allocation rules)
__device__ float g_pA[NROW * RANK];   // p, A-fragment layout (32KB / 128-row blk)
__device__ float g_pB[NROW * RANK];   // p, B-fragment layout
__device__ float g_sq[NROW];          // row squared norms (of tf32-rounded p)
__device__ float g_pf[DIM * RANK];    // proj tf32 B-fragments, 16 chunks of 4096

// ---------------- helpers ----------------
__device__ __forceinline__ uint32_t smem_u32(const void* p) {
    uint32_t a;
    asm("{ .reg .u64 t; cvta.to.shared.u64 t, %1; cvt.u32.u64 %0, t; }"
        : "=r"(a) : "l"(p));
    return a;
}
__device__ __forceinline__ void cpasync16(uint32_t s, const void* g) {
    asm volatile("cp.async.cg.shared.global [%0], [%1], 16;"
                 :: "r"(s), "l"(g) : "memory");
}
__device__ __forceinline__ uint32_t tf32u(float f) {
    uint32_t t;
    asm("cvt.rna.tf32.f32 %0, %1;" : "=r"(t) : "f"(f));
    return t;
}
__device__ __forceinline__ float tf32r(float f) { return __uint_as_float(tf32u(f)); }
__device__ __forceinline__ void mma_tf32(float* d, const uint32_t* a,
                                         uint32_t b0, uint32_t b1) {
    asm volatile(
        "mma.sync.aligned.m16n8k8.row.col.f32.tf32.tf32.f32 "
        "{%0,%1,%2,%3}, {%4,%5,%6,%7}, {%8,%9}, {%0,%1,%2,%3};"
        : "+f"(d[0]), "+f"(d[1]), "+f"(d[2]), "+f"(d[3])
        : "r"(a[0]), "r"(a[1]), "r"(a[2]), "r"(a[3]), "r"(b0), "r"(b1));
}

// ============================================================
// Kernel 0: proj -> tf32 B-fragment chunks (once). float4-vectorized.
// ============================================================
__global__ void __launch_bounds__(256) prep_proj_kernel(
    const float* __restrict__ proj) {
    int idx = blockIdx.x * 256 + threadIdx.x;   // 16384 float4s
    int k = idx >> 4, n4 = (idx & 15) << 2;
    float4 v = *(const float4*)(proj + (size_t)k * RANK + n4);
    int chunk = k >> 6, kk = k & 63;
    int kt = kk >> 3, f = (kk >> 2) & 1, k3 = kk & 3;
    float* dst = g_pf + chunk * 4096;
    const float* vp = (const float*)&v;
#pragma unroll
    for (int j = 0; j < 4; j++) {
        int n = n4 + j;
        dst[((n >> 3) * 8 + kt) * 64 + ((n & 7) * 4 + k3) * 2 + f] = tf32r(vp[j]);
    }
}

// ============================================================
// Kernel 1: proj GEMM. 256 CTAs x 64 rows, K=1024 in 16 chunks.
// 3-stage cp.async pipeline. Warps: 4 in M x 2 in N.
// ============================================================
#define XST 68
#define XBUF (64 * XST)
#define PBUF 4096
#define STAGE (XBUF + PBUF)
#define PROJ_SMEM (3 * STAGE * 4)   // 101376 B -> 2 CTA/SM

__global__ void __launch_bounds__(256, 2) proj_mma_kernel(
    const float* __restrict__ x) {
    extern __shared__ __align__(16) float smf[];
    __shared__ float s_part[2][64];

    const int tid = threadIdx.x, wid = tid >> 5, lane = tid & 31;
    const int gid = lane >> 2, tig = lane & 3;
    const int wm = wid & 3, wn = wid >> 2;
    const int rowbase = blockIdx.x * 64;
    const uint32_t sbase = smem_u32(smf);

    float acc[4][4];
#pragma unroll
    for (int i = 0; i < 4; i++)
#pragma unroll
        for (int j = 0; j < 4; j++) acc[i][j] = 0.f;

    auto load_stage = [&](int it, int buf) {
        const uint32_t sb = sbase + (uint32_t)(buf * STAGE) * 4;
        const float* src = x + (size_t)rowbase * DIM + it * 64;
#pragma unroll
        for (int l = 0; l < 4; l++) {
            int idx = tid + l * 256;
            int r = idx >> 4, c4 = (idx & 15) << 2;
            cpasync16(sb + (uint32_t)(r * XST + c4) * 4,
                      src + (size_t)r * DIM + c4);
        }
        const float* pf = g_pf + it * PBUF;
#pragma unroll
        for (int l = 0; l < 4; l++) {
            int idx = tid + l * 256;
            cpasync16(sb + (uint32_t)(XBUF + idx * 4) * 4, pf + idx * 4);
        }
        asm volatile("cp.async.commit_group;" ::: "memory");
    };

    load_stage(0, 0);
    load_stage(1, 1);
    load_stage(2, 2);

    int buf = 0;
    for (int it = 0; it < 16; ++it) {
        if (it <= 13)      asm volatile("cp.async.wait_group 2;" ::: "memory");
        else if (it == 14) asm volatile("cp.async.wait_group 1;" ::: "memory");
        else               asm volatile("cp.async.wait_group 0;" ::: "memory");
        __syncthreads();

        const float* xb = smf + buf * STAGE;
        const float* pb = xb + XBUF;
        const int r0 = wm * 16 + gid;
#pragma unroll
        for (int kt = 0; kt < 8; kt++) {
            const int c = kt * 8 + tig;
            uint32_t a[4];
            a[0] = tf32u(xb[r0 * XST + c]);
            a[1] = tf32u(xb[(r0 + 8) * XST + c]);
            a[2] = tf32u(xb[r0 * XST + c + 4]);
            a[3] = tf32u(xb[(r0 + 8) * XST + c + 4]);
#pragma unroll
            for (int nt = 0; nt < 4; nt++) {
                const int ng = wn * 4 + nt;
                const uint2 bb = *(const uint2*)(pb + (ng * 8 + kt) * 64 + lane * 2);
                mma_tf32(acc[nt], a, bb.x, bb.y);
            }
        }
        __syncthreads();
        if (it + 3 < 16) load_stage(it + 3, buf);
        buf = (buf == 2) ? 0 : buf + 1;
    }

    // ---- epilogue: round to tf32, sq norms, scatter to fragment layouts ----
    float vals[4][4];
    float sq1 = 0.f, sq2 = 0.f;
#pragma unroll
    for (int nt = 0; nt < 4; nt++) {
#pragma unroll
        for (int j = 0; j < 4; j++) vals[nt][j] = tf32r(acc[nt][j]);
        sq1 += vals[nt][0] * vals[nt][0] + vals[nt][1] * vals[nt][1];
        sq2 += vals[nt][2] * vals[nt][2] + vals[nt][3] * vals[nt][3];
    }
    sq1 += __shfl_xor_sync(0xffffffffu, sq1, 1);
    sq1 += __shfl_xor_sync(0xffffffffu, sq1, 2);
    sq2 += __shfl_xor_sync(0xffffffffu, sq2, 1);
    sq2 += __shfl_xor_sync(0xffffffffu, sq2, 2);

    const int r1 = wm * 16 + gid, r2 = r1 + 8;
    if (tig == 0) {
        s_part[wn][r1] = sq1;
        s_part[wn][r2] = sq2;
    }
    __syncthreads();
    if (tid < 64) g_sq[rowbase + tid] = s_part[0][tid] + s_part[1][tid];

    const int bb = blockIdx.x >> 1;
    const int half = (blockIdx.x & 1) * 64;
    float* gA = g_pA + (size_t)bb * 8192;
    float* gB = g_pB + (size_t)bb * 8192;
#pragma unroll
    for (int nt = 0; nt < 4; nt++) {
#pragma unroll
        for (int jj = 0; jj < 4; jj++) {
            const int lr = half + ((jj >= 2) ? r2 : r1);
            const int c = wn * 32 + nt * 8 + 2 * tig + (jj & 1);
            const float v = vals[nt][jj];
            {   // A-fragment layout
                int mt = lr >> 4, kt = c >> 3, rr = lr & 15, cc = c & 7;
                gA[(mt * 8 + kt) * 128 + ((rr & 7) * 4 + (cc & 3)) * 4 +
                   (rr >> 3) + 2 * (cc >> 2)] = v;
            }
            {   // B-fragment layout
                int ntb = lr >> 3, kt = c >> 3, nn = lr & 7, kkb = c & 7;
                gB[(ntb * 8 + kt) * 64 + (nn * 4 + (kkb & 3)) * 2 + (kkb >> 2)] = v;
            }
        }
    }
}

// ============================================================
// Kernel 2: dist, symmetric, 256 threads (8 warps, 64x32 warp tile).
// Off-diagonal transposed tile written DIRECTLY from registers
// (STG.32, sector-coalesced via gid-consecutive rows) — no smem
// round-trip, no extra barriers.
// ============================================================
#define DIST_SMEM (16384 * 4)   // 64 KB (two 32KB operand tiles)

__global__ void __launch_bounds__(256, 2) dist_mma_kernel(
    float* __restrict__ out) {
    extern __shared__ __align__(16) float smf[];
    __shared__ float s_sqA[128], s_sqB[128];

    const int tid = threadIdx.x, wid = tid >> 5, lane = tid & 31;
    const int gid = lane >> 2, tig = lane & 3;
    const int bz = blockIdx.z;

    // decode upper-triangular (i <= j) tile index
    const int t = blockIdx.x;
    int i = (int)(32.5f - sqrtf(32.5f * 32.5f - 2.0f * (float)t));
    if (i > 31) i = 31;
    while (i > 0 && (i * 32 - i * (i - 1) / 2) > t) i--;
    while (((i + 1) * 32 - (i + 1) * i / 2) <= t) i++;
    const int j = i + (t - (i * 32 - i * (i - 1) / 2));

    const int ablk = bz * NTILE + i, bblk = bz * NTILE + j;
    const uint32_t sbase = smem_u32(smf);

    const float4* gA = (const float4*)(g_pA + (size_t)ablk * 8192);
    const float4* gB = (const float4*)(g_pB + (size_t)bblk * 8192);
#pragma unroll
    for (int l = 0; l < 8; l++) {
        int idx = tid + l * 256;
        cpasync16(sbase + (uint32_t)idx * 16, gA + idx);
        cpasync16(sbase + 32768u + (uint32_t)idx * 16, gB + idx);
    }
    asm volatile("cp.async.commit_group;" ::: "memory");
    if (tid < 128) s_sqA[tid] = g_sq[ablk * 128 + tid];
    else           s_sqB[tid - 128] = g_sq[bblk * 128 + (tid - 128)];
    asm volatile("cp.async.wait_group 0;" ::: "memory");
    __syncthreads();

    const int wm = wid & 1, wn = wid >> 1;
    const float* As = smf;
    const float* Bs = smf + 8192;

    float acc[4][4][4];
#pragma unroll
    for (int a = 0; a < 4; a++)
#pragma unroll
        for (int b = 0; b < 4; b++)
#pragma unroll
            for (int c = 0; c < 4; c++) acc[a][b][c] = 0.f;

#pragma unroll
    for (int kt = 0; kt < 8; kt++) {
        uint4 a[4];
        uint2 b[4];
#pragma unroll
        for (int mt = 0; mt < 4; mt++)
            a[mt] = *(const uint4*)(As + ((wm * 4 + mt) * 8 + kt) * 128 + lane * 4);
#pragma unroll
        for (int nt = 0; nt < 4; nt++)
            b[nt] = *(const uint2*)(Bs + ((wn * 4 + nt) * 8 + kt) * 64 + lane * 2);
#pragma unroll
        for (int mt = 0; mt < 4; mt++)
#pragma unroll
            for (int nt = 0; nt < 4; nt++)
                mma_tf32(acc[mt][nt], (const uint32_t*)&a[mt], b[nt].x, b[nt].y);
    }

    // ---- finalize values (clamped distances) in regs ----
#pragma unroll
    for (int mt = 0; mt < 4; mt++) {
        const int rl1 = wm * 64 + mt * 16 + gid, rl2 = rl1 + 8;
        const float sA1 = s_sqA[rl1], sA2 = s_sqA[rl2];
#pragma unroll
        for (int nt = 0; nt < 4; nt++) {
            const int cl = wn * 32 + nt * 8 + 2 * tig;
            const float sB0 = s_sqB[cl], sB1 = s_sqB[cl + 1];
            acc[mt][nt][0] = fmaxf(sA1 + sB0 - 2.f * acc[mt][nt][0], 0.f);
            acc[mt][nt][1] = fmaxf(sA1 + sB1 - 2.f * acc[mt][nt][1], 0.f);
            acc[mt][nt][2] = fmaxf(sA2 + sB0 - 2.f * acc[mt][nt][2], 0.f);
            acc[mt][nt][3] = fmaxf(sA2 + sB1 - 2.f * acc[mt][nt][3], 0.f);
        }
    }

    // ---- direct tile write (rows i-block, cols j-block) ----
#pragma unroll
    for (int mt = 0; mt < 4; mt++) {
        const int rl1 = wm * 64 + mt * 16 + gid;
        float* o1 = out + ((size_t)bz * SEQ + i * 128 + rl1) * SEQ + j * 128;
        float* o2 = o1 + (size_t)8 * SEQ;
#pragma unroll
        for (int nt = 0; nt < 4; nt++) {
            const int cl = wn * 32 + nt * 8 + 2 * tig;
            __stcs((float2*)(o1 + cl), make_float2(acc[mt][nt][0], acc[mt][nt][1]));
            __stcs((float2*)(o2 + cl), make_float2(acc[mt][nt][2], acc[mt][nt][3]));
        }
    }

    // ---- transposed tile write directly from registers (off-diag) ----
    if (i != j) {
        float* tb = out + ((size_t)bz * SEQ + j * 128) * SEQ + i * 128;
#pragma unroll
        for (int nt = 0; nt < 4; nt++) {
            const int cl = wn * 32 + nt * 8 + 2 * tig;
            float* c0 = tb + (size_t)cl * SEQ;
            float* c1 = c0 + SEQ;
#pragma unroll
            for (int mt = 0; mt < 4; mt++) {
                const int rl1 = wm * 64 + mt * 16 + gid;
                __stcs(c0 + rl1,     acc[mt][nt][0]);
                __stcs(c1 + rl1,     acc[mt][nt][1]);
                __stcs(c0 + rl1 + 8, acc[mt][nt][2]);
                __stcs(c1 + rl1 + 8, acc[mt][nt][3]);
            }
        }
    }
}

// ============================================================
extern "C" void kernel_launch(void* const* d_in, const int* in_sizes, int n_in,
                              void* d_out, int out_size) {
    const float* x = (const float*)d_in[0];
    const float* proj = (const float*)d_in[1];
    float* out = (float*)d_out;

    prep_proj_kernel<<<64, 256>>>(proj);

    cudaFuncSetAttribute(proj_mma_kernel,
                         cudaFuncAttributeMaxDynamicSharedMemorySize, PROJ_SMEM);
    proj_mma_kernel<<<NROW / 64, 256, PROJ_SMEM>>>(x);

    cudaFuncSetAttribute(dist_mma_kernel,
                         cudaFuncAttributeMaxDynamicSharedMemorySize, DIST_SMEM);
    dim3 grid(TRI, 1, BATCH);
    dist_mma_kernel<<<grid, 256, DIST_SMEM>>>(out);
}

// round 9
// speedup vs baseline: 1.5316x; 1.1268x over previous
#include <cuda_runtime.h>
#include <cuda_fp16.h>
#include <cstdint>

#define SEQ   4096
#define BATCH 4
#define DIM   1024
#define RANK  64
#define NROW  (BATCH * SEQ)   // 16384
#define NTILE 32
#define TRI   528             // upper-tri tiles per batch
#define OFFD  496             // off-diagonal tiles per batch

// Scratch (__device__ globals per allocation rules)
__device__ __half g_pA16[NROW * RANK];  // p fp16, A-fragment layout (16KB/128-blk)
__device__ __half g_pB16[NROW * RANK];  // p fp16, B-fragment layout
__device__ float  g_sq[NROW];           // row sq norms (of fp16-rounded p)
__device__ float  g_pf[DIM * RANK];     // proj tf32 B-fragments (16 chunks x 4096)

// ---------------- helpers ----------------
__device__ __forceinline__ uint32_t smem_u32(const void* p) {
    uint32_t a;
    asm("{ .reg .u64 t; cvta.to.shared.u64 t, %1; cvt.u32.u64 %0, t; }"
        : "=r"(a) : "l"(p));
    return a;
}
__device__ __forceinline__ void cpasync16(uint32_t s, const void* g) {
    asm volatile("cp.async.cg.shared.global [%0], [%1], 16;"
                 :: "r"(s), "l"(g) : "memory");
}
__device__ __forceinline__ uint32_t tf32u(float f) {
    uint32_t t;
    asm("cvt.rna.tf32.f32 %0, %1;" : "=r"(t) : "f"(f));
    return t;
}
__device__ __forceinline__ float tf32r(float f) { return __uint_as_float(tf32u(f)); }
__device__ __forceinline__ void mma_tf32(float* d, const uint32_t* a,
                                         uint32_t b0, uint32_t b1) {
    asm volatile(
        "mma.sync.aligned.m16n8k8.row.col.f32.tf32.tf32.f32 "
        "{%0,%1,%2,%3}, {%4,%5,%6,%7}, {%8,%9}, {%0,%1,%2,%3};"
        : "+f"(d[0]), "+f"(d[1]), "+f"(d[2]), "+f"(d[3])
        : "r"(a[0]), "r"(a[1]), "r"(a[2]), "r"(a[3]), "r"(b0), "r"(b1));
}
__device__ __forceinline__ void mma_f16(float* d, const uint32_t* a,
                                        uint32_t b0, uint32_t b1) {
    asm volatile(
        "mma.sync.aligned.m16n8k16.row.col.f32.f16.f16.f32 "
        "{%0,%1,%2,%3}, {%4,%5,%6,%7}, {%8,%9}, {%0,%1,%2,%3};"
        : "+f"(d[0]), "+f"(d[1]), "+f"(d[2]), "+f"(d[3])
        : "r"(a[0]), "r"(a[1]), "r"(a[2]), "r"(a[3]), "r"(b0), "r"(b1));
}

// ============================================================
// Kernel 0: proj -> tf32 B-fragment chunks (once). 128x128 launch.
// ============================================================
__global__ void __launch_bounds__(128) prep_proj_kernel(
    const float* __restrict__ proj) {
    int idx = blockIdx.x * 128 + threadIdx.x;   // 16384 float4s
    int k = idx >> 4, n4 = (idx & 15) << 2;
    float4 v = *(const float4*)(proj + (size_t)k * RANK + n4);
    int chunk = k >> 6, kk = k & 63;
    int kt = kk >> 3, f = (kk >> 2) & 1, k3 = kk & 3;
    float* dst = g_pf + chunk * 4096;
    const float* vp = (const float*)&v;
#pragma unroll
    for (int j = 0; j < 4; j++) {
        int n = n4 + j;
        dst[((n >> 3) * 8 + kt) * 64 + ((n & 7) * 4 + k3) * 2 + f] = tf32r(vp[j]);
    }
}

// ============================================================
// Kernel 1: proj GEMM (tf32). 256 CTAs x 64 rows, K=1024, 3-stage pipe.
// Epilogue: round p to fp16, sq norms, scatter to fp16 mma-fragment
// layouts (m16n8k16 A and B).
// ============================================================
#define XST 68
#define XBUF (64 * XST)
#define PBUF 4096
#define STAGE (XBUF + PBUF)
#define PROJ_SMEM (3 * STAGE * 4)   // 101376 B -> 2 CTA/SM

__global__ void __launch_bounds__(256, 2) proj_mma_kernel(
    const float* __restrict__ x) {
    extern __shared__ __align__(16) float smf[];
    __shared__ float s_part[2][64];

    const int tid = threadIdx.x, wid = tid >> 5, lane = tid & 31;
    const int gid = lane >> 2, tig = lane & 3;
    const int wm = wid & 3, wn = wid >> 2;
    const int rowbase = blockIdx.x * 64;
    const uint32_t sbase = smem_u32(smf);

    float acc[4][4];
#pragma unroll
    for (int i = 0; i < 4; i++)
#pragma unroll
        for (int j = 0; j < 4; j++) acc[i][j] = 0.f;

    auto load_stage = [&](int it, int buf) {
        const uint32_t sb = sbase + (uint32_t)(buf * STAGE) * 4;
        const float* src = x + (size_t)rowbase * DIM + it * 64;
#pragma unroll
        for (int l = 0; l < 4; l++) {
            int idx = tid + l * 256;
            int r = idx >> 4, c4 = (idx & 15) << 2;
            cpasync16(sb + (uint32_t)(r * XST + c4) * 4,
                      src + (size_t)r * DIM + c4);
        }
        const float* pf = g_pf + it * PBUF;
#pragma unroll
        for (int l = 0; l < 4; l++) {
            int idx = tid + l * 256;
            cpasync16(sb + (uint32_t)(XBUF + idx * 4) * 4, pf + idx * 4);
        }
        asm volatile("cp.async.commit_group;" ::: "memory");
    };

    load_stage(0, 0);
    load_stage(1, 1);
    load_stage(2, 2);

    int buf = 0;
    for (int it = 0; it < 16; ++it) {
        if (it <= 13)      asm volatile("cp.async.wait_group 2;" ::: "memory");
        else if (it == 14) asm volatile("cp.async.wait_group 1;" ::: "memory");
        else               asm volatile("cp.async.wait_group 0;" ::: "memory");
        __syncthreads();

        const float* xb = smf + buf * STAGE;
        const float* pb = xb + XBUF;
        const int r0 = wm * 16 + gid;
#pragma unroll
        for (int kt = 0; kt < 8; kt++) {
            const int c = kt * 8 + tig;
            uint32_t a[4];
            a[0] = tf32u(xb[r0 * XST + c]);
            a[1] = tf32u(xb[(r0 + 8) * XST + c]);
            a[2] = tf32u(xb[r0 * XST + c + 4]);
            a[3] = tf32u(xb[(r0 + 8) * XST + c + 4]);
#pragma unroll
            for (int nt = 0; nt < 4; nt++) {
                const int ng = wn * 4 + nt;
                const uint2 bb = *(const uint2*)(pb + (ng * 8 + kt) * 64 + lane * 2);
                mma_tf32(acc[nt], a, bb.x, bb.y);
            }
        }
        __syncthreads();
        if (it + 3 < 16) load_stage(it + 3, buf);
        buf = (buf == 2) ? 0 : buf + 1;
    }

    // ---- epilogue: round to fp16, sq from rounded values, scatter ----
    __half hv[4][4];
    float sq1 = 0.f, sq2 = 0.f;
#pragma unroll
    for (int nt = 0; nt < 4; nt++) {
#pragma unroll
        for (int j = 0; j < 4; j++) {
            hv[nt][j] = __float2half_rn(acc[nt][j]);
            acc[nt][j] = __half2float(hv[nt][j]);
        }
        sq1 += acc[nt][0] * acc[nt][0] + acc[nt][1] * acc[nt][1];
        sq2 += acc[nt][2] * acc[nt][2] + acc[nt][3] * acc[nt][3];
    }
    sq1 += __shfl_xor_sync(0xffffffffu, sq1, 1);
    sq1 += __shfl_xor_sync(0xffffffffu, sq1, 2);
    sq2 += __shfl_xor_sync(0xffffffffu, sq2, 1);
    sq2 += __shfl_xor_sync(0xffffffffu, sq2, 2);

    const int r1 = wm * 16 + gid, r2 = r1 + 8;
    if (tig == 0) {
        s_part[wn][r1] = sq1;
        s_part[wn][r2] = sq2;
    }
    __syncthreads();
    if (tid < 64) g_sq[rowbase + tid] = s_part[0][tid] + s_part[1][tid];

    const int bb = blockIdx.x >> 1;
    const int half = (blockIdx.x & 1) * 64;
    __half* gA = g_pA16 + (size_t)bb * 8192;
    __half* gB = g_pB16 + (size_t)bb * 8192;
#pragma unroll
    for (int nt = 0; nt < 4; nt++) {
#pragma unroll
        for (int jj = 0; jj < 4; jj++) {
            const int lr = half + ((jj >= 2) ? r2 : r1);
            const int c = wn * 32 + nt * 8 + 2 * tig + (jj & 1);
            const __half v = hv[nt][jj];
            const int cc = c & 15, kt = c >> 4, hf = cc & 1;
            {   // A-fragment (m16n8k16 row-major): regs a0..a3
                int mt = lr >> 4, r = lr & 15;
                int q = ((r >> 3) & 1) | ((cc >= 8) ? 2 : 0);
                int ln = (r & 7) * 4 + ((cc & 7) >> 1);
                gA[((mt * 4 + kt) * 32 + ln) * 8 + q * 2 + hf] = v;
            }
            {   // B-fragment (n8k16 col-major): regs b0,b1
                int ntb = lr >> 3, gd = lr & 7;
                int q = (cc >= 8) ? 1 : 0;
                int ln = gd * 4 + ((cc & 7) >> 1);
                gB[((ntb * 4 + kt) * 32 + ln) * 4 + q * 2 + hf] = v;
            }
        }
    }
}

// ============================================================
// Kernel 2: dist fp16, symmetric, 256 threads (8 warps, 64x32 warp
// tile). Tiles ordered off-diagonal first, diagonal last (tail smoothing).
// ============================================================
#define DIST_SMEM (8192 * 4)   // 32 KB (two 16KB fp16 operand tiles)

__global__ void __launch_bounds__(256, 2) dist_mma_kernel(
    float* __restrict__ out) {
    extern __shared__ __align__(16) uint32_t sm32[];
    __shared__ float s_sqA[128], s_sqB[128];

    const int tid = threadIdx.x, wid = tid >> 5, lane = tid & 31;
    const int gid = lane >> 2, tig = lane & 3;
    const int bz = blockIdx.z;

    // tile decode: t < OFFD -> off-diag (i<j, j-major); else diagonal
    const int t = blockIdx.x;
    int i, j;
    if (t < OFFD) {
        j = (int)((1.f + sqrtf(1.f + 8.f * (float)t)) * 0.5f);
        while (j * (j - 1) / 2 > t) j--;
        while ((j + 1) * j / 2 <= t) j++;
        i = t - j * (j - 1) / 2;
    } else {
        i = j = t - OFFD;
    }

    const int ablk = bz * NTILE + i, bblk = bz * NTILE + j;
    const uint32_t sbase = smem_u32(sm32);

    const float4* gA = (const float4*)(g_pA16 + (size_t)ablk * 8192);
    const float4* gB = (const float4*)(g_pB16 + (size_t)bblk * 8192);
#pragma unroll
    for (int l = 0; l < 4; l++) {
        int idx = tid + l * 256;
        cpasync16(sbase + (uint32_t)idx * 16, gA + idx);
        cpasync16(sbase + 16384u + (uint32_t)idx * 16, gB + idx);
    }
    asm volatile("cp.async.commit_group;" ::: "memory");
    if (tid < 128) s_sqA[tid] = g_sq[ablk * 128 + tid];
    else           s_sqB[tid - 128] = g_sq[bblk * 128 + (tid - 128)];
    asm volatile("cp.async.wait_group 0;" ::: "memory");
    __syncthreads();

    const int wm = wid & 1, wn = wid >> 1;
    const uint32_t* As = sm32;          // 4096 u32
    const uint32_t* Bs = sm32 + 4096;   // 4096 u32

    float acc[4][4][4];
#pragma unroll
    for (int a = 0; a < 4; a++)
#pragma unroll
        for (int b = 0; b < 4; b++)
#pragma unroll
            for (int c = 0; c < 4; c++) acc[a][b][c] = 0.f;

#pragma unroll
    for (int kt = 0; kt < 4; kt++) {
        uint4 a[4];
        uint2 b[4];
#pragma unroll
        for (int mt = 0; mt < 4; mt++)
            a[mt] = *(const uint4*)(As + ((wm * 4 + mt) * 4 + kt) * 128 + lane * 4);
#pragma unroll
        for (int nt = 0; nt < 4; nt++)
            b[nt] = *(const uint2*)(Bs + ((wn * 4 + nt) * 4 + kt) * 64 + lane * 2);
#pragma unroll
        for (int mt = 0; mt < 4; mt++)
#pragma unroll
            for (int nt = 0; nt < 4; nt++)
                mma_f16(acc[mt][nt], (const uint32_t*)&a[mt], b[nt].x, b[nt].y);
    }

    // ---- finalize values (clamped distances) in regs ----
#pragma unroll
    for (int mt = 0; mt < 4; mt++) {
        const int rl1 = wm * 64 + mt * 16 + gid, rl2 = rl1 + 8;
        const float sA1 = s_sqA[rl1], sA2 = s_sqA[rl2];
#pragma unroll
        for (int nt = 0; nt < 4; nt++) {
            const int cl = wn * 32 + nt * 8 + 2 * tig;
            const float sB0 = s_sqB[cl], sB1 = s_sqB[cl + 1];
            acc[mt][nt][0] = fmaxf(sA1 + sB0 - 2.f * acc[mt][nt][0], 0.f);
            acc[mt][nt][1] = fmaxf(sA1 + sB1 - 2.f * acc[mt][nt][1], 0.f);
            acc[mt][nt][2] = fmaxf(sA2 + sB0 - 2.f * acc[mt][nt][2], 0.f);
            acc[mt][nt][3] = fmaxf(sA2 + sB1 - 2.f * acc[mt][nt][3], 0.f);
        }
    }

    // ---- direct tile write (rows i-block, cols j-block) ----
#pragma unroll
    for (int mt = 0; mt < 4; mt++) {
        const int rl1 = wm * 64 + mt * 16 + gid;
        float* o1 = out + ((size_t)bz * SEQ + i * 128 + rl1) * SEQ + j * 128;
        float* o2 = o1 + (size_t)8 * SEQ;
#pragma unroll
        for (int nt = 0; nt < 4; nt++) {
            const int cl = wn * 32 + nt * 8 + 2 * tig;
            __stcs((float2*)(o1 + cl), make_float2(acc[mt][nt][0], acc[mt][nt][1]));
            __stcs((float2*)(o2 + cl), make_float2(acc[mt][nt][2], acc[mt][nt][3]));
        }
    }

    // ---- transposed tile write directly from registers (off-diag) ----
    if (i != j) {
        float* tb = out + ((size_t)bz * SEQ + j * 128) * SEQ + i * 128;
#pragma unroll
        for (int nt = 0; nt < 4; nt++) {
            const int cl = wn * 32 + nt * 8 + 2 * tig;
            float* c0 = tb + (size_t)cl * SEQ;
            float* c1 = c0 + SEQ;
#pragma unroll
            for (int mt = 0; mt < 4; mt++) {
                const int rl1 = wm * 64 + mt * 16 + gid;
                __stcs(c0 + rl1,     acc[mt][nt][0]);
                __stcs(c1 + rl1,     acc[mt][nt][1]);
                __stcs(c0 + rl1 + 8, acc[mt][nt][2]);
                __stcs(c1 + rl1 + 8, acc[mt][nt][3]);
            }
        }
    }
}

// ============================================================
extern "C" void kernel_launch(void* const* d_in, const int* in_sizes, int n_in,
                              void* d_out, int out_size) {
    const float* x = (const float*)d_in[0];
    const float* proj = (const float*)d_in[1];
    float* out = (float*)d_out;

    prep_proj_kernel<<<128, 128>>>(proj);

    cudaFuncSetAttribute(proj_mma_kernel,
                         cudaFuncAttributeMaxDynamicSharedMemorySize, PROJ_SMEM);
    proj_mma_kernel<<<NROW / 64, 256, PROJ_SMEM>>>(x);

    cudaFuncSetAttribute(dist_mma_kernel,
                         cudaFuncAttributeMaxDynamicSharedMemorySize, DIST_SMEM);
    dim3 grid(TRI, 1, BATCH);
    dist_mma_kernel<<<grid, 256, DIST_SMEM>>>(out);
}